// round 11
// baseline (speedup 1.0000x reference)
#include <cuda_runtime.h>
#include <math.h>

#define BN 16
#define UPD 512
#define NPIX (UPD*UPD)
#define PATCH 120
#define NM 4
#define TPB 256
#define SW 168           // smem tile cols
#define SH 56            // smem tile rows

// ---------------- static device scratch (zero-initialized at load) ----------------
__device__ float g_inv[3*BN*6];                 // inverse thetas: [which][b][6]
__device__ float g_bufA[BN*NPIX];               // pred_trans
__device__ float g_bufB[BN*NPIX];               // pred_rot
__device__ float g_rm2[NM*BN*NPIX];             // mask after g2 sample (zero outside boxes)
__device__ int4  g_srcpart[NM*8];               // per-j partial src bboxes
__device__ int4  g_box1[NM*BN];                 // stage-1 write box (r0,c0,h,w)
__device__ int4  g_box2[NM*BN];                 // stage-2 box (r0,c0,h,w)
__device__ float g_com[NM*BN*3];                // per (j,b): tot, sx, sy

// ---------------- helpers ----------------
__device__ __forceinline__ float bilin_sample(const float* __restrict__ s,
                                              float gx, float gy, int H, int W) {
    // torch grid_sample: bilinear, zero padding, align_corners=False
    float x = ((gx + 1.0f) * (float)W - 1.0f) * 0.5f;
    float y = ((gy + 1.0f) * (float)H - 1.0f) * 0.5f;
    float xf = floorf(x), yf = floorf(y);
    int x0 = (int)xf, y0 = (int)yf;
    float wx = x - xf, wy = y - yf;
    int x1 = x0 + 1, y1 = y0 + 1;
    bool xi0 = (x0 >= 0) && (x0 < W);
    bool xi1 = (x1 >= 0) && (x1 < W);
    bool yi0 = (y0 >= 0) && (y0 < H);
    bool yi1 = (y1 >= 0) && (y1 < H);
    float v00 = 0.f, v01 = 0.f, v10 = 0.f, v11 = 0.f;
    if (yi0) {
        const float* row = s + y0 * W;
        if (xi0) v00 = __ldg(row + x0);
        if (xi1) v01 = __ldg(row + x1);
    }
    if (yi1) {
        const float* row = s + y1 * W;
        if (xi0) v10 = __ldg(row + x0);
        if (xi1) v11 = __ldg(row + x1);
    }
    return (1.f - wx) * (1.f - wy) * v00 + wx * (1.f - wy) * v01
         + (1.f - wx) * wy * v10 + wx * wy * v11;
}

// ---------------- K0: 2x3 affine inverses ----------------
__global__ void k_inv(const float* __restrict__ sc, const float* __restrict__ ro,
                      const float* __restrict__ tr) {
    int t = threadIdx.x;
    if (t >= 3 * BN) return;
    int w = t / BN, b = t % BN;
    const float* src = (w == 0) ? sc : ((w == 1) ? ro : tr);
    const float* m = src + b * 6;
    float a = m[0], bb = m[1], c = m[2], d = m[3], e = m[4], f = m[5];
    float det = a * e - bb * d;
    float ia = e / det, ib = -bb / det, id = -d / det, ie = a / det;
    float ic  = -(ia * c + ib * f);
    float iff = -(id * c + ie * f);
    float* o = g_inv + t * 6;
    o[0] = ia; o[1] = ib; o[2] = ic; o[3] = id; o[4] = ie; o[5] = iff;
}

// ---------------- source mask bbox (partials) ----------------
__global__ void k_srcbox(const float* __restrict__ masks) {
    int j = blockIdx.y, seg = blockIdx.x;
    const float* m = masks + j * NPIX;
    int base = seg * (NPIX / 8);
    int rmin = 1 << 20, rmax = -1, cmin = 1 << 20, cmax = -1;
    for (int k = threadIdx.x; k < NPIX / 8; k += TPB) {
        int g = base + k;
        if (m[g] != 0.0f) {
            int r = g >> 9, c = g & 511;
            rmin = min(rmin, r); rmax = max(rmax, r);
            cmin = min(cmin, c); cmax = max(cmax, c);
        }
    }
    __shared__ int s0[TPB], s1[TPB], s2[TPB], s3[TPB];
    s0[threadIdx.x] = rmin; s1[threadIdx.x] = rmax;
    s2[threadIdx.x] = cmin; s3[threadIdx.x] = cmax;
    __syncthreads();
    for (int s = TPB / 2; s > 0; s >>= 1) {
        if (threadIdx.x < s) {
            s0[threadIdx.x] = min(s0[threadIdx.x], s0[threadIdx.x + s]);
            s1[threadIdx.x] = max(s1[threadIdx.x], s1[threadIdx.x + s]);
            s2[threadIdx.x] = min(s2[threadIdx.x], s2[threadIdx.x + s]);
            s3[threadIdx.x] = max(s3[threadIdx.x], s3[threadIdx.x + s]);
        }
        __syncthreads();
    }
    if (threadIdx.x == 0)
        g_srcpart[j * 8 + seg] = make_int4(s0[0], s1[0], s2[0], s3[0]);
}

// ---------------- affine preimage of a pixel rect ----------------
__device__ __forceinline__ void preimage_px(const float* th,
        float ya, float yb, float xa, float xb,
        int& ir0, int& ir1, int& ic0, int& ic1) {
    float gxa = (2.f * xa + 1.f) / 512.f - 1.f, gxb = (2.f * xb + 1.f) / 512.f - 1.f;
    float gya = (2.f * ya + 1.f) / 512.f - 1.f, gyb = (2.f * yb + 1.f) / 512.f - 1.f;
    float det = th[0] * th[4] - th[1] * th[3];
    float Xmin = 1e30f, Xmax = -1e30f, Ymin = 1e30f, Ymax = -1e30f;
    #pragma unroll
    for (int u = 0; u < 4; u++) {
        float gx = (u & 1) ? gxb : gxa;
        float gy = (u & 2) ? gyb : gya;
        float rx = gx - th[2], ry = gy - th[5];
        float X = ( th[4] * rx - th[1] * ry) / det;
        float Y = (-th[3] * rx + th[0] * ry) / det;
        Xmin = fminf(Xmin, X); Xmax = fmaxf(Xmax, X);
        Ymin = fminf(Ymin, Y); Ymax = fmaxf(Ymax, Y);
    }
    float jmin = ((Xmin + 1.f) * 512.f - 1.f) * 0.5f;
    float jmax = ((Xmax + 1.f) * 512.f - 1.f) * 0.5f;
    float imin = ((Ymin + 1.f) * 512.f - 1.f) * 0.5f;
    float imax = ((Ymax + 1.f) * 512.f - 1.f) * 0.5f;
    ir0 = max(0,   (int)floorf(imin) - 1);
    ir1 = min(511, (int)ceilf(imax) + 1);
    ic0 = max(0,   (int)floorf(jmin) - 1);
    ic1 = min(511, (int)ceilf(jmax) + 1);
}

// ---------------- per-(j,b) output boxes (needs g_inv + g_srcpart) ----------------
__global__ void k_boxes() {
    int t = threadIdx.x;
    if (t >= NM * BN) return;
    int j = t / BN, b = t % BN;
    int r0 = 1 << 20, r1 = -1, c0 = 1 << 20, c1 = -1;
    for (int k = 0; k < 8; k++) {
        int4 p = g_srcpart[j * 8 + k];
        r0 = min(r0, p.x); r1 = max(r1, p.y);
        c0 = min(c0, p.z); c1 = max(c1, p.w);
    }
    if (r1 < r0) {
        g_box1[t] = make_int4(0, 0, 0, 0);
        g_box2[t] = make_int4(0, 0, 0, 0);
        return;
    }
    int a0, a1, b0, b1;
    preimage_px(g_inv + (BN + b) * 6,
                (float)r0 - 1.f, (float)r1 + 1.f,
                (float)c0 - 1.f, (float)c1 + 1.f, a0, a1, b0, b1);
    int w0 = max(0, a0 - 2), w1 = min(511, a1 + 2);
    int w2 = max(0, b0 - 2), w3 = min(511, b1 + 2);
    g_box1[t] = make_int4(w0, w2, w1 - w0 + 1, w3 - w2 + 1);
    int d0, d1, e0, e1;
    preimage_px(g_inv + b * 6,
                (float)a0 - 1.f, (float)a1 + 1.f,
                (float)b0 - 1.f, (float)b1 + 1.f, d0, d1, e0, e1);
    d0 = max(0, d0 - 1); d1 = min(511, d1 + 1);
    e0 = max(0, e0 - 1); e1 = min(511, e1 + 1);
    g_box2[t] = make_int4(d0, e0, d1 - d0 + 1, e1 - e0 + 1);
}

// ---------------- K1: jax.image.resize linear, 4 outputs/thread ----------------
__global__ void k_resize4(const float* __restrict__ base, float* __restrict__ out) {
    int idx = blockIdx.x * blockDim.x + threadIdx.x;
    if (idx >= BN * NPIX / 4) return;
    int b = idx / (NPIX / 4), r4 = idx - b * (NPIX / 4);
    int i = r4 >> 7;
    int j0 = (r4 & 127) * 4;
    float fy = (i + 0.5f) * 0.25f - 0.5f;
    fy = fminf(fmaxf(fy, 0.f), 127.f);
    int y0 = (int)fy;
    float wy = fy - (float)y0;
    int y1 = min(y0 + 1, 127);
    const float* p = base + b * 128 * 128;
    const float* r0 = p + y0 * 128;
    const float* r1 = p + y1 * 128;
    float4 o;
    #pragma unroll
    for (int q = 0; q < 4; q++) {
        float fx = (j0 + q + 0.5f) * 0.25f - 0.5f;
        fx = fminf(fmaxf(fx, 0.f), 127.f);
        int x0 = (int)fx;
        float wx = fx - (float)x0;
        int x1 = min(x0 + 1, 127);
        float top = (1.f - wx) * __ldg(r0 + x0) + wx * __ldg(r0 + x1);
        float bot = (1.f - wx) * __ldg(r1 + x0) + wx * __ldg(r1 + x1);
        ((float*)&o)[q] = (1.f - wy) * top + wy * bot;
    }
    ((float4*)out)[idx] = o;
}

// ---------------- image warp with smem source staging ----------------
// Block (32,8): output tile 128x8. Stage the tile's source bbox into smem
// (coalesced), take bilinear taps from smem. Zero-fill outside the image
// reproduces zero-padding exactly. Fallback to global gathers if the bbox
// exceeds the smem window (data-dependent, correctness-preserving).
__global__ void k_warp_sm(const float* __restrict__ src, float* __restrict__ dst,
                          float* __restrict__ dst2, int thoff) {
    __shared__ float tile[SH * SW];
    __shared__ int sb[4];          // r0s, c0s, h, w
    __shared__ int sfall;
    int b = blockIdx.z;
    int i0 = blockIdx.y * 8;
    int j0t = blockIdx.x * 128;
    const float* th = g_inv + (thoff + b) * 6;
    float t0 = th[0], t1 = th[1], t2 = th[2], t3 = th[3], t4 = th[4], t5 = th[5];
    int tid = threadIdx.y * 32 + threadIdx.x;

    if (tid == 0) {
        float xmin = 1e30f, xmax = -1e30f, ymin = 1e30f, ymax = -1e30f;
        #pragma unroll
        for (int u = 0; u < 4; u++) {
            int jj = (u & 1) ? (j0t + 127) : j0t;
            int ii = (u & 2) ? (i0 + 7) : i0;
            float X = (float)(2 * jj + 1) / 512.0f - 1.0f;
            float Y = (float)(2 * ii + 1) / 512.0f - 1.0f;
            float gx = t0 * X + t1 * Y + t2;
            float gy = t3 * X + t4 * Y + t5;
            float x = ((gx + 1.0f) * 512.0f - 1.0f) * 0.5f;
            float y = ((gy + 1.0f) * 512.0f - 1.0f) * 0.5f;
            xmin = fminf(xmin, x); xmax = fmaxf(xmax, x);
            ymin = fminf(ymin, y); ymax = fmaxf(ymax, y);
        }
        int c0s = (int)floorf(xmin) - 1;
        int c1s = (int)floorf(xmax) + 2;
        int r0s = (int)floorf(ymin) - 1;
        int r1s = (int)floorf(ymax) + 2;
        int w = c1s - c0s + 1, h = r1s - r0s + 1;
        sb[0] = r0s; sb[1] = c0s; sb[2] = h; sb[3] = w;
        sfall = (w > SW || h > SH) ? 1 : 0;
    }
    __syncthreads();

    const float* s = src + b * NPIX;
    int fall = sfall;
    int r0s = sb[0], c0s = sb[1], h = sb[2], w = sb[3];

    if (!fall) {
        // coalesced staging with zero-fill outside the image
        for (int t = tid; t < h * w; t += 256) {
            int r = t / w, c = t - r * w;
            int gr = r0s + r, gc = c0s + c;
            float v = 0.f;
            if (gr >= 0 && gr < UPD && gc >= 0 && gc < UPD)
                v = __ldg(s + (gr << 9) + gc);
            tile[r * SW + c] = v;
        }
        __syncthreads();
    }

    int i = i0 + threadIdx.y;
    int j0 = j0t + threadIdx.x * 4;
    float Y = (float)(2 * i + 1) / 512.0f - 1.0f;
    float4 o;
    #pragma unroll
    for (int q = 0; q < 4; q++) {
        float X = (float)(2 * (j0 + q) + 1) / 512.0f - 1.0f;
        float gx = t0 * X + t1 * Y + t2;
        float gy = t3 * X + t4 * Y + t5;
        float v;
        if (!fall) {
            float x = ((gx + 1.0f) * 512.0f - 1.0f) * 0.5f;
            float y = ((gy + 1.0f) * 512.0f - 1.0f) * 0.5f;
            float xf = floorf(x), yf = floorf(y);
            float wx = x - xf, wy = y - yf;
            int sx = (int)xf - c0s, sy = (int)yf - r0s;
            const float* rA = tile + sy * SW + sx;
            float v00 = rA[0], v01 = rA[1];
            float v10 = rA[SW], v11 = rA[SW + 1];
            v = (1.f - wx) * (1.f - wy) * v00 + wx * (1.f - wy) * v01
              + (1.f - wx) * wy * v10 + wx * wy * v11;
        } else {
            v = bilin_sample(s, gx, gy, UPD, UPD);
        }
        ((float*)&o)[q] = v;
    }
    int idx4 = (b * NPIX + (i << 9) + j0) >> 2;
    ((float4*)dst)[idx4] = o;
    if (dst2) ((float4*)dst2)[idx4] = o;
}

// ---------------- mask stage 1 (box-restricted, side stream) ----------------
__global__ void k_mask1(const float* __restrict__ masks) {
    int jb = blockIdx.y;
    int j = jb / BN, b = jb % BN;
    int4 bx = g_box1[jb];
    int area = bx.z * bx.w;
    const float* th = g_inv + (BN + b) * 6;
    float t0 = th[0], t1 = th[1], t2 = th[2], t3 = th[3], t4 = th[4], t5 = th[5];
    const float* s = masks + j * NPIX;
    float* dst = g_rm2 + (size_t)jb * NPIX;
    for (int t = blockIdx.x * TPB + threadIdx.x; t < area; t += 8 * TPB) {
        int i = bx.x + t / bx.w, jj = bx.y + t % bx.w;
        float X = (float)(2 * jj + 1) / 512.0f - 1.0f;
        float Y = (float)(2 * i + 1) / 512.0f - 1.0f;
        float gx = t0 * X + t1 * Y + t2;
        float gy = t3 * X + t4 * Y + t5;
        dst[(i << 9) + jj] = bilin_sample(s, gx, gy, UPD, UPD);
    }
}

// ---------------- FUSED mask stage 2 + threshold + COM: one block per (j,b) ----------------
__global__ void k_mask23(const float* __restrict__ img_all, float* __restrict__ mrot) {
    int jb = blockIdx.x;
    int b = jb % BN;
    int tid = threadIdx.x;
    const int NT = 1024;
    __shared__ float sh1[NT], sh2[NT], sh3[NT];
    __shared__ float sh_thr;

    int4 bx = g_box2[jb];
    int area = bx.z * bx.w;
    const float* th = g_inv + b * 6;
    float t0 = th[0], t1 = th[1], t2 = th[2], t3 = th[3], t4 = th[4], t5 = th[5];
    const float* src = g_rm2 + (size_t)jb * NPIX;
    const float* img = img_all + b * NPIX;
    float* dst = mrot + (size_t)jb * NPIX;
    float sn = 0.f, sm = 0.f;
    for (int t = tid; t < area; t += NT) {
        int i = bx.x + t / bx.w, jj = bx.y + t % bx.w;
        float X = (float)(2 * jj + 1) / 512.0f - 1.0f;
        float Y = (float)(2 * i + 1) / 512.0f - 1.0f;
        float gx = t0 * X + t1 * Y + t2;
        float gy = t3 * X + t4 * Y + t5;
        float v = bilin_sample(src, gx, gy, UPD, UPD);
        int g = (i << 9) + jj;
        bool on = (v >= 0.5f);
        dst[g] = on ? 1.0f : 0.0f;
        if (on) { sn += img[g]; sm += 1.0f; }
    }
    sh1[tid] = sn; sh2[tid] = sm;
    __syncthreads();
    for (int s = NT / 2; s > 0; s >>= 1) {
        if (tid < s) { sh1[tid] += sh1[tid + s]; sh2[tid] += sh2[tid + s]; }
        __syncthreads();
    }
    if (tid == 0) sh_thr = (sh1[0] / fmaxf(sh2[0], 1.0f)) * 1.5f;
    __syncthreads();
    float thr = sh_thr;

    float st = 0.f, sx = 0.f, sy = 0.f;
    for (int t = tid; t < area; t += NT) {
        int i = bx.x + t / bx.w, jj = bx.y + t % bx.w;
        int g = (i << 9) + jj;
        if (dst[g] > 0.5f) {
            float nv = img[g];
            if (nv > thr) {
                st += nv;
                sx += nv * (float)i;
                sy += nv * (float)jj;
            }
        }
    }
    sh1[tid] = st; sh2[tid] = sx; sh3[tid] = sy;
    __syncthreads();
    for (int s = NT / 2; s > 0; s >>= 1) {
        if (tid < s) {
            sh1[tid] += sh1[tid + s];
            sh2[tid] += sh2[tid + s];
            sh3[tid] += sh3[tid + s];
        }
        __syncthreads();
    }
    if (tid == 0) {
        g_com[jb * 3 + 0] = sh1[0];
        g_com[jb * 3 + 1] = sh2[0];
        g_com[jb * 3 + 2] = sh3[0];
    }
}

// ---------------- revise: one block per batch item; patch in dynamic smem ----------------
__global__ void k_revise(float* __restrict__ rev, const float* __restrict__ adj) {
    extern __shared__ float patch[];   // PATCH*PATCH floats = 57.6KB
    int b = blockIdx.x;
    int tid = threadIdx.x;
    float a = adj[b];
    float* img = rev + b * NPIX;
    const float* th = g_inv + b * 6;  // inv(scaler_shear)
    __shared__ int sh_xy[2];
    for (int j = 0; j < NM; j++) {
        if (tid == 0) {
            int o = (j * BN + b) * 3;
            float tot = g_com[o] + 1e-8f;
            float cx = g_com[o + 1] / tot, cy = g_com[o + 2] / tot;
            int x0 = __float2int_rn(cx) - 60;            // round half to even
            int y0 = __float2int_rn(cy) - 60;
            x0 = min(max(x0, 0), UPD - PATCH);           // dynamic_slice clamping
            y0 = min(max(y0, 0), UPD - PATCH);
            sh_xy[0] = x0; sh_xy[1] = y0;
        }
        __syncthreads();
        int x0 = sh_xy[0], y0 = sh_xy[1];
        for (int t = tid; t < PATCH * PATCH; t += blockDim.x) {
            int p = t / PATCH, q = t - p * PATCH;
            float v = img[(x0 + p) * UPD + (y0 + q)];
            int dp = p - 60, dq = q - 60;
            if (dp * dp + dq * dq <= 16) v = v / a;
            patch[t] = v;
        }
        __syncthreads();
        for (int t = tid; t < PATCH * PATCH; t += blockDim.x) {
            int p = t / PATCH, q = t - p * PATCH;
            float X = (float)(2 * q + 1) / 120.0f - 1.0f;
            float Y = (float)(2 * p + 1) / 120.0f - 1.0f;
            float gx = th[0] * X + th[1] * Y + th[2];
            float gy = th[3] * X + th[4] * Y + th[5];
            float x = ((gx + 1.0f) * 120.0f - 1.0f) * 0.5f;
            float y = ((gy + 1.0f) * 120.0f - 1.0f) * 0.5f;
            float xf = floorf(x), yf = floorf(y);
            int xx0 = (int)xf, yy0 = (int)yf;
            float wx = x - xf, wy = y - yf;
            int xx1 = xx0 + 1, yy1 = yy0 + 1;
            bool xi0 = (xx0 >= 0) && (xx0 < PATCH);
            bool xi1 = (xx1 >= 0) && (xx1 < PATCH);
            bool yi0 = (yy0 >= 0) && (yy0 < PATCH);
            bool yi1 = (yy1 >= 0) && (yy1 < PATCH);
            float v00 = (yi0 && xi0) ? patch[yy0 * PATCH + xx0] : 0.f;
            float v01 = (yi0 && xi1) ? patch[yy0 * PATCH + xx1] : 0.f;
            float v10 = (yi1 && xi0) ? patch[yy1 * PATCH + xx0] : 0.f;
            float v11 = (yi1 && xi1) ? patch[yy1 * PATCH + xx1] : 0.f;
            float v = (1.f - wx) * (1.f - wy) * v00 + wx * (1.f - wy) * v01
                    + (1.f - wx) * wy * v10 + wx * wy * v11;
            img[(x0 + p) * UPD + (y0 + q)] = v;
        }
        __syncthreads();
    }
}

// ---------------- launch ----------------
extern "C" void kernel_launch(void* const* d_in, const int* in_sizes, int n_in,
                              void* d_out, int out_size) {
    const float* base  = (const float*)d_in[0];
    const float* sc    = (const float*)d_in[1];
    const float* ro    = (const float*)d_in[2];
    const float* tr    = (const float*)d_in[3];
    const float* adj   = (const float*)d_in[4];
    const float* masks = (const float*)d_in[5];
    float* out = (float*)d_out;
    float* seg0 = out;                           // base_inp
    float* seg1 = out + (size_t)BN * NPIX;       // pred_input
    float* seg2 = out + (size_t)2 * BN * NPIX;   // pred_revise
    float* seg3 = out + (size_t)3 * BN * NPIX;   // masks_rot

    float *bufA, *bufB;
    cudaGetSymbolAddress((void**)&bufA, g_bufA);
    cudaGetSymbolAddress((void**)&bufB, g_bufB);

    // One-time resource setup on the FIRST (uncaptured) call; reused during
    // capture so no driver allocations occur inside the graph lifetime.
    // (Exactly ONE extra stream — the 2-stream topology is proven clean;
    // >=3 extra streams leave 2MB of graph-upload allocations live.)
    static cudaStream_t s1 = nullptr;
    static cudaEvent_t evRoot, evInv, evS1;
    static bool init_done = false;
    if (!init_done) {
        cudaFuncSetAttribute(k_revise, cudaFuncAttributeMaxDynamicSharedMemorySize,
                             PATCH * PATCH * (int)sizeof(float));
        cudaStreamCreateWithFlags(&s1, cudaStreamNonBlocking);
        cudaEventCreateWithFlags(&evRoot, cudaEventDisableTiming);
        cudaEventCreateWithFlags(&evInv, cudaEventDisableTiming);
        cudaEventCreateWithFlags(&evS1, cudaEventDisableTiming);
        init_done = true;
    }

    int nblk_img4 = (BN * NPIX / 4 + TPB - 1) / TPB;
    dim3 wgrid(4, 64, BN), wblk(32, 8);

    // fork
    cudaEventRecord(evRoot, 0);
    cudaStreamWaitEvent(s1, evRoot, 0);

    // main chain (default stream)
    k_inv<<<1, 64>>>(sc, ro, tr);
    cudaEventRecord(evInv, 0);
    k_resize4<<<nblk_img4, TPB>>>(base, seg0);
    k_warp_sm<<<wgrid, wblk>>>(seg0, bufA, nullptr, 2 * BN);    // inv(translation)
    k_warp_sm<<<wgrid, wblk>>>(bufA, bufB, nullptr, 1 * BN);    // inv(rotation)
    k_warp_sm<<<wgrid, wblk>>>(bufB, seg1, seg2, 0);            // inv(shear)

    // side branch s1: memset + srcbox + boxes + mask1 (independent of image chain)
    cudaMemsetAsync(seg3, 0, (size_t)NM * BN * NPIX * sizeof(float), s1);
    k_srcbox<<<dim3(8, NM), TPB, 0, s1>>>(masks);
    cudaStreamWaitEvent(s1, evInv, 0);
    k_boxes<<<1, 64, 0, s1>>>();
    k_mask1<<<dim3(8, NM * BN), TPB, 0, s1>>>(masks);
    cudaEventRecord(evS1, s1);

    // join, fused mask stage2+COM, revise
    cudaStreamWaitEvent(0, evS1, 0);
    k_mask23<<<NM * BN, 1024>>>(seg1, seg3);
    k_revise<<<BN, 1024, PATCH * PATCH * sizeof(float)>>>(seg2, adj);
}

// round 12
// speedup vs baseline: 1.2914x; 1.2914x over previous
#include <cuda_runtime.h>
#include <math.h>

#define BN 16
#define UPD 512
#define NPIX (UPD*UPD)
#define PATCH 120
#define NM 4
#define TPB 256

// ---------------- static device scratch (zero-initialized at load) ----------------
__device__ float g_inv[3*BN*6];                 // inverse thetas: [which][b][6]
__device__ float g_bufA[BN*NPIX];               // pred_trans
__device__ float g_bufB[BN*NPIX];               // pred_rot
__device__ float g_rm2[NM*BN*NPIX];             // mask after g2 sample (zero outside boxes)
__device__ int4  g_srcpart[NM*8];               // per-j partial src bboxes
__device__ int4  g_box1[NM*BN];                 // stage-1 write box (r0,c0,h,w)
__device__ int4  g_box2[NM*BN];                 // stage-2 box (r0,c0,h,w)
__device__ float g_com[NM*BN*3];                // per (j,b): tot, sx, sy

// ---------------- helpers ----------------
__device__ __forceinline__ float bilin_sample(const float* __restrict__ s,
                                              float gx, float gy, int H, int W) {
    // torch grid_sample: bilinear, zero padding, align_corners=False
    float x = ((gx + 1.0f) * (float)W - 1.0f) * 0.5f;
    float y = ((gy + 1.0f) * (float)H - 1.0f) * 0.5f;
    float xf = floorf(x), yf = floorf(y);
    int x0 = (int)xf, y0 = (int)yf;
    float wx = x - xf, wy = y - yf;
    int x1 = x0 + 1, y1 = y0 + 1;
    bool xi0 = (x0 >= 0) && (x0 < W);
    bool xi1 = (x1 >= 0) && (x1 < W);
    bool yi0 = (y0 >= 0) && (y0 < H);
    bool yi1 = (y1 >= 0) && (y1 < H);
    float v00 = 0.f, v01 = 0.f, v10 = 0.f, v11 = 0.f;
    if (yi0) {
        const float* row = s + y0 * W;
        if (xi0) v00 = __ldg(row + x0);
        if (xi1) v01 = __ldg(row + x1);
    }
    if (yi1) {
        const float* row = s + y1 * W;
        if (xi0) v10 = __ldg(row + x0);
        if (xi1) v11 = __ldg(row + x1);
    }
    return (1.f - wx) * (1.f - wy) * v00 + wx * (1.f - wy) * v01
         + (1.f - wx) * wy * v10 + wx * wy * v11;
}

// ---------------- K0: 2x3 affine inverses ----------------
__global__ void k_inv(const float* __restrict__ sc, const float* __restrict__ ro,
                      const float* __restrict__ tr) {
    int t = threadIdx.x;
    if (t >= 3 * BN) return;
    int w = t / BN, b = t % BN;
    const float* src = (w == 0) ? sc : ((w == 1) ? ro : tr);
    const float* m = src + b * 6;
    float a = m[0], bb = m[1], c = m[2], d = m[3], e = m[4], f = m[5];
    float det = a * e - bb * d;
    float ia = e / det, ib = -bb / det, id = -d / det, ie = a / det;
    float ic  = -(ia * c + ib * f);
    float iff = -(id * c + ie * f);
    float* o = g_inv + t * 6;
    o[0] = ia; o[1] = ib; o[2] = ic; o[3] = id; o[4] = ie; o[5] = iff;
}

// ---------------- source mask bbox (partials) ----------------
__global__ void k_srcbox(const float* __restrict__ masks) {
    int j = blockIdx.y, seg = blockIdx.x;
    const float* m = masks + j * NPIX;
    int base = seg * (NPIX / 8);
    int rmin = 1 << 20, rmax = -1, cmin = 1 << 20, cmax = -1;
    for (int k = threadIdx.x; k < NPIX / 8; k += TPB) {
        int g = base + k;
        if (m[g] != 0.0f) {
            int r = g >> 9, c = g & 511;
            rmin = min(rmin, r); rmax = max(rmax, r);
            cmin = min(cmin, c); cmax = max(cmax, c);
        }
    }
    __shared__ int s0[TPB], s1[TPB], s2[TPB], s3[TPB];
    s0[threadIdx.x] = rmin; s1[threadIdx.x] = rmax;
    s2[threadIdx.x] = cmin; s3[threadIdx.x] = cmax;
    __syncthreads();
    for (int s = TPB / 2; s > 0; s >>= 1) {
        if (threadIdx.x < s) {
            s0[threadIdx.x] = min(s0[threadIdx.x], s0[threadIdx.x + s]);
            s1[threadIdx.x] = max(s1[threadIdx.x], s1[threadIdx.x + s]);
            s2[threadIdx.x] = min(s2[threadIdx.x], s2[threadIdx.x + s]);
            s3[threadIdx.x] = max(s3[threadIdx.x], s3[threadIdx.x + s]);
        }
        __syncthreads();
    }
    if (threadIdx.x == 0)
        g_srcpart[j * 8 + seg] = make_int4(s0[0], s1[0], s2[0], s3[0]);
}

// ---------------- affine preimage of a pixel rect ----------------
__device__ __forceinline__ void preimage_px(const float* th,
        float ya, float yb, float xa, float xb,
        int& ir0, int& ir1, int& ic0, int& ic1) {
    float gxa = (2.f * xa + 1.f) / 512.f - 1.f, gxb = (2.f * xb + 1.f) / 512.f - 1.f;
    float gya = (2.f * ya + 1.f) / 512.f - 1.f, gyb = (2.f * yb + 1.f) / 512.f - 1.f;
    float det = th[0] * th[4] - th[1] * th[3];
    float Xmin = 1e30f, Xmax = -1e30f, Ymin = 1e30f, Ymax = -1e30f;
    #pragma unroll
    for (int u = 0; u < 4; u++) {
        float gx = (u & 1) ? gxb : gxa;
        float gy = (u & 2) ? gyb : gya;
        float rx = gx - th[2], ry = gy - th[5];
        float X = ( th[4] * rx - th[1] * ry) / det;
        float Y = (-th[3] * rx + th[0] * ry) / det;
        Xmin = fminf(Xmin, X); Xmax = fmaxf(Xmax, X);
        Ymin = fminf(Ymin, Y); Ymax = fmaxf(Ymax, Y);
    }
    float jmin = ((Xmin + 1.f) * 512.f - 1.f) * 0.5f;
    float jmax = ((Xmax + 1.f) * 512.f - 1.f) * 0.5f;
    float imin = ((Ymin + 1.f) * 512.f - 1.f) * 0.5f;
    float imax = ((Ymax + 1.f) * 512.f - 1.f) * 0.5f;
    ir0 = max(0,   (int)floorf(imin) - 1);
    ir1 = min(511, (int)ceilf(imax) + 1);
    ic0 = max(0,   (int)floorf(jmin) - 1);
    ic1 = min(511, (int)ceilf(jmax) + 1);
}

// ---------------- per-(j,b) output boxes (needs g_inv + g_srcpart) ----------------
__global__ void k_boxes() {
    int t = threadIdx.x;
    if (t >= NM * BN) return;
    int j = t / BN, b = t % BN;
    int r0 = 1 << 20, r1 = -1, c0 = 1 << 20, c1 = -1;
    for (int k = 0; k < 8; k++) {
        int4 p = g_srcpart[j * 8 + k];
        r0 = min(r0, p.x); r1 = max(r1, p.y);
        c0 = min(c0, p.z); c1 = max(c1, p.w);
    }
    if (r1 < r0) {
        g_box1[t] = make_int4(0, 0, 0, 0);
        g_box2[t] = make_int4(0, 0, 0, 0);
        return;
    }
    int a0, a1, b0, b1;
    preimage_px(g_inv + (BN + b) * 6,
                (float)r0 - 1.f, (float)r1 + 1.f,
                (float)c0 - 1.f, (float)c1 + 1.f, a0, a1, b0, b1);
    int w0 = max(0, a0 - 2), w1 = min(511, a1 + 2);
    int w2 = max(0, b0 - 2), w3 = min(511, b1 + 2);
    g_box1[t] = make_int4(w0, w2, w1 - w0 + 1, w3 - w2 + 1);
    int d0, d1, e0, e1;
    preimage_px(g_inv + b * 6,
                (float)a0 - 1.f, (float)a1 + 1.f,
                (float)b0 - 1.f, (float)b1 + 1.f, d0, d1, e0, e1);
    d0 = max(0, d0 - 1); d1 = min(511, d1 + 1);
    e0 = max(0, e0 - 1); e1 = min(511, e1 + 1);
    g_box2[t] = make_int4(d0, e0, d1 - d0 + 1, e1 - e0 + 1);
}

// ---------------- K1: jax.image.resize linear, 4 outputs/thread ----------------
__global__ void k_resize4(const float* __restrict__ base, float* __restrict__ out) {
    int idx = blockIdx.x * blockDim.x + threadIdx.x;
    if (idx >= BN * NPIX / 4) return;
    int b = idx / (NPIX / 4), r4 = idx - b * (NPIX / 4);
    int i = r4 >> 7;
    int j0 = (r4 & 127) * 4;
    float fy = (i + 0.5f) * 0.25f - 0.5f;
    fy = fminf(fmaxf(fy, 0.f), 127.f);
    int y0 = (int)fy;
    float wy = fy - (float)y0;
    int y1 = min(y0 + 1, 127);
    const float* p = base + b * 128 * 128;
    const float* r0 = p + y0 * 128;
    const float* r1 = p + y1 * 128;
    float4 o;
    #pragma unroll
    for (int q = 0; q < 4; q++) {
        float fx = (j0 + q + 0.5f) * 0.25f - 0.5f;
        fx = fminf(fmaxf(fx, 0.f), 127.f);
        int x0 = (int)fx;
        float wx = fx - (float)x0;
        int x1 = min(x0 + 1, 127);
        float top = (1.f - wx) * __ldg(r0 + x0) + wx * __ldg(r0 + x1);
        float bot = (1.f - wx) * __ldg(r1 + x0) + wx * __ldg(r1 + x1);
        ((float*)&o)[q] = (1.f - wy) * top + wy * bot;
    }
    ((float4*)out)[idx] = o;
}

// ---------------- image warp, square 32x32 tile, 4 rows/thread ----------------
// Block (32,8): output tile 32 cols x 32 rows. Thread (tx,ty) computes rows
// ty, ty+8, ty+16, ty+24 at column tx. Source footprint ~38x38 (vs 134x34 for
// the 128x8 tile) -> ~3x less L1 sector traffic on gathers.
__global__ void k_warp4sq(const float* __restrict__ src, float* __restrict__ dst,
                          float* __restrict__ dst2, int thoff) {
    int b = blockIdx.z;
    int i0 = blockIdx.y * 32 + threadIdx.y;
    int j  = blockIdx.x * 32 + threadIdx.x;
    const float* th = g_inv + (thoff + b) * 6;
    float t0 = th[0], t1 = th[1], t2 = th[2], t3 = th[3], t4 = th[4], t5 = th[5];
    float X = (float)(2 * j + 1) / 512.0f - 1.0f;
    float gxX = t0 * X + t2;       // column-dependent parts
    float gyX = t3 * X + t5;
    const float* s = src + b * NPIX;
    float v[4];
    #pragma unroll
    for (int q = 0; q < 4; q++) {
        int i = i0 + q * 8;
        float Y = (float)(2 * i + 1) / 512.0f - 1.0f;
        float gx = gxX + t1 * Y;
        float gy = gyX + t4 * Y;
        v[q] = bilin_sample(s, gx, gy, UPD, UPD);
    }
    int base_idx = b * NPIX + (i0 << 9) + j;
    #pragma unroll
    for (int q = 0; q < 4; q++) {
        dst[base_idx + (q << 12)] = v[q];          // (q*8)<<9 = q<<12
        if (dst2) dst2[base_idx + (q << 12)] = v[q];
    }
}

// ---------------- mask stage 1 (box-restricted, side stream) ----------------
__global__ void k_mask1(const float* __restrict__ masks) {
    int jb = blockIdx.y;
    int j = jb / BN, b = jb % BN;
    int4 bx = g_box1[jb];
    int area = bx.z * bx.w;
    const float* th = g_inv + (BN + b) * 6;
    float t0 = th[0], t1 = th[1], t2 = th[2], t3 = th[3], t4 = th[4], t5 = th[5];
    const float* s = masks + j * NPIX;
    float* dst = g_rm2 + (size_t)jb * NPIX;
    for (int t = blockIdx.x * TPB + threadIdx.x; t < area; t += 8 * TPB) {
        int i = bx.x + t / bx.w, jj = bx.y + t % bx.w;
        float X = (float)(2 * jj + 1) / 512.0f - 1.0f;
        float Y = (float)(2 * i + 1) / 512.0f - 1.0f;
        float gx = t0 * X + t1 * Y + t2;
        float gy = t3 * X + t4 * Y + t5;
        dst[(i << 9) + jj] = bilin_sample(s, gx, gy, UPD, UPD);
    }
}

// ---------------- FUSED mask stage 2 + threshold + COM: one block per (j,b) ----------------
__global__ void k_mask23(const float* __restrict__ img_all, float* __restrict__ mrot) {
    int jb = blockIdx.x;
    int b = jb % BN;
    int tid = threadIdx.x;
    const int NT = 1024;
    __shared__ float sh1[NT], sh2[NT], sh3[NT];
    __shared__ float sh_thr;

    int4 bx = g_box2[jb];
    int area = bx.z * bx.w;
    const float* th = g_inv + b * 6;
    float t0 = th[0], t1 = th[1], t2 = th[2], t3 = th[3], t4 = th[4], t5 = th[5];
    const float* src = g_rm2 + (size_t)jb * NPIX;
    const float* img = img_all + b * NPIX;
    float* dst = mrot + (size_t)jb * NPIX;
    float sn = 0.f, sm = 0.f;
    for (int t = tid; t < area; t += NT) {
        int i = bx.x + t / bx.w, jj = bx.y + t % bx.w;
        float X = (float)(2 * jj + 1) / 512.0f - 1.0f;
        float Y = (float)(2 * i + 1) / 512.0f - 1.0f;
        float gx = t0 * X + t1 * Y + t2;
        float gy = t3 * X + t4 * Y + t5;
        float v = bilin_sample(src, gx, gy, UPD, UPD);
        int g = (i << 9) + jj;
        bool on = (v >= 0.5f);
        dst[g] = on ? 1.0f : 0.0f;
        if (on) { sn += img[g]; sm += 1.0f; }
    }
    sh1[tid] = sn; sh2[tid] = sm;
    __syncthreads();
    for (int s = NT / 2; s > 0; s >>= 1) {
        if (tid < s) { sh1[tid] += sh1[tid + s]; sh2[tid] += sh2[tid + s]; }
        __syncthreads();
    }
    if (tid == 0) sh_thr = (sh1[0] / fmaxf(sh2[0], 1.0f)) * 1.5f;
    __syncthreads();
    float thr = sh_thr;

    float st = 0.f, sx = 0.f, sy = 0.f;
    for (int t = tid; t < area; t += NT) {
        int i = bx.x + t / bx.w, jj = bx.y + t % bx.w;
        int g = (i << 9) + jj;
        if (dst[g] > 0.5f) {
            float nv = img[g];
            if (nv > thr) {
                st += nv;
                sx += nv * (float)i;
                sy += nv * (float)jj;
            }
        }
    }
    sh1[tid] = st; sh2[tid] = sx; sh3[tid] = sy;
    __syncthreads();
    for (int s = NT / 2; s > 0; s >>= 1) {
        if (tid < s) {
            sh1[tid] += sh1[tid + s];
            sh2[tid] += sh2[tid + s];
            sh3[tid] += sh3[tid + s];
        }
        __syncthreads();
    }
    if (tid == 0) {
        g_com[jb * 3 + 0] = sh1[0];
        g_com[jb * 3 + 1] = sh2[0];
        g_com[jb * 3 + 2] = sh3[0];
    }
}

// ---------------- revise: one block per batch item; patch in dynamic smem ----------------
__global__ void k_revise(float* __restrict__ rev, const float* __restrict__ adj) {
    extern __shared__ float patch[];   // PATCH*PATCH floats = 57.6KB
    int b = blockIdx.x;
    int tid = threadIdx.x;
    float a = adj[b];
    float* img = rev + b * NPIX;
    const float* th = g_inv + b * 6;  // inv(scaler_shear)
    __shared__ int sh_xy[2];
    for (int j = 0; j < NM; j++) {
        if (tid == 0) {
            int o = (j * BN + b) * 3;
            float tot = g_com[o] + 1e-8f;
            float cx = g_com[o + 1] / tot, cy = g_com[o + 2] / tot;
            int x0 = __float2int_rn(cx) - 60;            // round half to even
            int y0 = __float2int_rn(cy) - 60;
            x0 = min(max(x0, 0), UPD - PATCH);           // dynamic_slice clamping
            y0 = min(max(y0, 0), UPD - PATCH);
            sh_xy[0] = x0; sh_xy[1] = y0;
        }
        __syncthreads();
        int x0 = sh_xy[0], y0 = sh_xy[1];
        for (int t = tid; t < PATCH * PATCH; t += blockDim.x) {
            int p = t / PATCH, q = t - p * PATCH;
            float v = img[(x0 + p) * UPD + (y0 + q)];
            int dp = p - 60, dq = q - 60;
            if (dp * dp + dq * dq <= 16) v = v / a;
            patch[t] = v;
        }
        __syncthreads();
        for (int t = tid; t < PATCH * PATCH; t += blockDim.x) {
            int p = t / PATCH, q = t - p * PATCH;
            float X = (float)(2 * q + 1) / 120.0f - 1.0f;
            float Y = (float)(2 * p + 1) / 120.0f - 1.0f;
            float gx = th[0] * X + th[1] * Y + th[2];
            float gy = th[3] * X + th[4] * Y + th[5];
            float x = ((gx + 1.0f) * 120.0f - 1.0f) * 0.5f;
            float y = ((gy + 1.0f) * 120.0f - 1.0f) * 0.5f;
            float xf = floorf(x), yf = floorf(y);
            int xx0 = (int)xf, yy0 = (int)yf;
            float wx = x - xf, wy = y - yf;
            int xx1 = xx0 + 1, yy1 = yy0 + 1;
            bool xi0 = (xx0 >= 0) && (xx0 < PATCH);
            bool xi1 = (xx1 >= 0) && (xx1 < PATCH);
            bool yi0 = (yy0 >= 0) && (yy0 < PATCH);
            bool yi1 = (yy1 >= 0) && (yy1 < PATCH);
            float v00 = (yi0 && xi0) ? patch[yy0 * PATCH + xx0] : 0.f;
            float v01 = (yi0 && xi1) ? patch[yy0 * PATCH + xx1] : 0.f;
            float v10 = (yi1 && xi0) ? patch[yy1 * PATCH + xx0] : 0.f;
            float v11 = (yi1 && xi1) ? patch[yy1 * PATCH + xx1] : 0.f;
            float v = (1.f - wx) * (1.f - wy) * v00 + wx * (1.f - wy) * v01
                    + (1.f - wx) * wy * v10 + wx * wy * v11;
            img[(x0 + p) * UPD + (y0 + q)] = v;
        }
        __syncthreads();
    }
}

// ---------------- launch ----------------
extern "C" void kernel_launch(void* const* d_in, const int* in_sizes, int n_in,
                              void* d_out, int out_size) {
    const float* base  = (const float*)d_in[0];
    const float* sc    = (const float*)d_in[1];
    const float* ro    = (const float*)d_in[2];
    const float* tr    = (const float*)d_in[3];
    const float* adj   = (const float*)d_in[4];
    const float* masks = (const float*)d_in[5];
    float* out = (float*)d_out;
    float* seg0 = out;                           // base_inp
    float* seg1 = out + (size_t)BN * NPIX;       // pred_input
    float* seg2 = out + (size_t)2 * BN * NPIX;   // pred_revise
    float* seg3 = out + (size_t)3 * BN * NPIX;   // masks_rot

    float *bufA, *bufB;
    cudaGetSymbolAddress((void**)&bufA, g_bufA);
    cudaGetSymbolAddress((void**)&bufB, g_bufB);

    // One-time resource setup on the FIRST (uncaptured) call; reused during
    // capture so no driver allocations occur inside the graph lifetime.
    static cudaStream_t s1 = nullptr;
    static cudaEvent_t evRoot, evInv, evS1;
    static bool init_done = false;
    if (!init_done) {
        cudaFuncSetAttribute(k_revise, cudaFuncAttributeMaxDynamicSharedMemorySize,
                             PATCH * PATCH * (int)sizeof(float));
        cudaStreamCreateWithFlags(&s1, cudaStreamNonBlocking);
        cudaEventCreateWithFlags(&evRoot, cudaEventDisableTiming);
        cudaEventCreateWithFlags(&evInv, cudaEventDisableTiming);
        cudaEventCreateWithFlags(&evS1, cudaEventDisableTiming);
        init_done = true;
    }

    int nblk_img4 = (BN * NPIX / 4 + TPB - 1) / TPB;
    dim3 wgrid(16, 16, BN), wblk(32, 8);

    // fork
    cudaEventRecord(evRoot, 0);
    cudaStreamWaitEvent(s1, evRoot, 0);

    // main chain (default stream)
    k_inv<<<1, 64>>>(sc, ro, tr);
    cudaEventRecord(evInv, 0);
    k_resize4<<<nblk_img4, TPB>>>(base, seg0);
    k_warp4sq<<<wgrid, wblk>>>(seg0, bufA, nullptr, 2 * BN);    // inv(translation)
    k_warp4sq<<<wgrid, wblk>>>(bufA, bufB, nullptr, 1 * BN);    // inv(rotation)
    k_warp4sq<<<wgrid, wblk>>>(bufB, seg1, seg2, 0);            // inv(shear)

    // side branch s1: memset + srcbox + boxes + mask1 (independent of image chain)
    cudaMemsetAsync(seg3, 0, (size_t)NM * BN * NPIX * sizeof(float), s1);
    k_srcbox<<<dim3(8, NM), TPB, 0, s1>>>(masks);
    cudaStreamWaitEvent(s1, evInv, 0);
    k_boxes<<<1, 64, 0, s1>>>();
    k_mask1<<<dim3(8, NM * BN), TPB, 0, s1>>>(masks);
    cudaEventRecord(evS1, s1);

    // join, fused mask stage2+COM, revise
    cudaStreamWaitEvent(0, evS1, 0);
    k_mask23<<<NM * BN, 1024>>>(seg1, seg3);
    k_revise<<<BN, 1024, PATCH * PATCH * sizeof(float)>>>(seg2, adj);
}